// round 1
// baseline (speedup 1.0000x reference)
#include <cuda_runtime.h>

#define B_   32
#define T_   512
#define H_   1024
#define G_   4096
#define L_   2
#define NCTA 128
#define NTHR 256
#define SMEM_BYTES ((B_*H_ + B_*32) * 4)

// Persistent state (allocation-free scratch: __device__ globals)
__device__ float g_h[2][L_][B_][H_];   // [buf][layer][b][u]
__device__ float g_c[L_][B_][H_];      // [layer][b][u]
__device__ unsigned g_bar_count = 0;
__device__ unsigned g_bar_gen   = 0;

__device__ __forceinline__ float sigmoidf_(float v) {
    return 1.0f / (1.0f + __expf(-v));
}

// Sense-free generation barrier: self-restoring across graph replays.
__device__ __forceinline__ void grid_sync() {
    __threadfence();          // make this CTA's global writes visible
    __syncthreads();
    if (threadIdx.x == 0) {
        unsigned gen = atomicAdd(&g_bar_gen, 0u);
        unsigned arrived = atomicAdd(&g_bar_count, 1u);
        if (arrived == NCTA - 1) {
            atomicExch(&g_bar_count, 0u);
            __threadfence();
            atomicAdd(&g_bar_gen, 1u);
        } else {
            while (atomicAdd(&g_bar_gen, 0u) == gen) { }
        }
        __threadfence();
    }
    __syncthreads();
}

// Stage x_t [32][1024] (strided per batch row) into SMEM
__device__ __forceinline__ void stage_x(const float* __restrict__ x, int t, float* sh) {
    #pragma unroll 8
    for (int i = 0; i < (B_*H_/4)/NTHR; i++) {
        int idx = threadIdx.x + i * NTHR;      // float4 index over [32][256]
        int b   = idx >> 8;
        int k4  = idx & 255;
        const float4* src = (const float4*)(x + (size_t)b * T_ * H_ + (size_t)t * H_);
        ((float4*)sh)[idx] = __ldg(src + k4);
    }
}

// Stage contiguous [32][1024] h buffer into SMEM, bypassing L1 (cross-CTA producer)
__device__ __forceinline__ void stage_h(const float* src, float* sh) {
    const float4* s4 = (const float4*)src;
    float4* d4 = (float4*)sh;
    #pragma unroll 8
    for (int i = 0; i < (B_*H_/4)/NTHR; i++) {
        int idx = threadIdx.x + i * NTHR;
        d4[idx] = __ldcg(s4 + idx);
    }
}

// Accumulate 2x2 output tile over K=1024: acts from SMEM, weights from L2
__device__ __forceinline__ void kloop(const float* sh_act, const float* __restrict__ W,
                                      int jcol, int r0,
                                      float& a00, float& a01, float& a10, float& a11) {
    const float2* wp  = (const float2*)(W + jcol);
    const float*  pa0 = sh_act + r0 * H_;
    const float*  pa1 = pa0 + H_;
    #pragma unroll 8
    for (int k = 0; k < H_; k++) {
        float2 w = __ldg(wp);
        wp += G_ / 2;                  // advance one weight row (4096 floats)
        float x0 = pa0[k];
        float x1 = pa1[k];
        a00 += x0 * w.x;  a01 += x0 * w.y;
        a10 += x1 * w.x;  a11 += x1 * w.y;
    }
}

extern "C" __global__ void __launch_bounds__(NTHR, 1)
lstm_persistent_kernel(const float* __restrict__ x,   // [B,T,H]
                       const float* __restrict__ Wx,  // [L,H,4H]
                       const float* __restrict__ Wh,  // [L,H,4H]
                       const float* __restrict__ bias,// [L,4H]
                       float* __restrict__ out)       // y[B,T,H] ++ h_f[L,B,H] ++ c_f[L,B,H]
{
    extern __shared__ float smem[];
    float* sh_act = smem;            // 32*1024 floats
    float* sh_z   = smem + B_ * H_;  // 32*32 floats

    const int cta = blockIdx.x;
    const int tid = threadIdx.x;

    // GEMM tile mapping: CTA owns units [cta*8, cta*8+8); 32 gate-cols x 32 batch rows
    const int cp   = tid & 15;          // col pair 0..15
    const int rp   = tid >> 4;          // row pair 0..15
    const int r0   = rp * 2;
    const int lc   = cp * 2;            // local col 0..30 (even)
    const int gate = lc >> 3;           // 0..3 (i,f,g,o)
    const int uu0  = lc & 7;
    const int u0   = cta * 8;
    const int jcol = gate * H_ + u0 + uu0;   // global gate column (pair: jcol, jcol+1)

    // Elementwise-update mapping: thread = (batch, unit)
    const int ub  = tid >> 3;   // 0..31
    const int uui = tid & 7;    // 0..7
    const int gu  = u0 + uui;   // owned hidden unit

    // ---- init state to zero (re-done every launch: deterministic) ----
    {
        float* ph = &g_h[0][0][0][0];
        const int th = 2 * L_ * B_ * H_;
        for (int i = cta * NTHR + tid; i < th; i += NCTA * NTHR) ph[i] = 0.0f;
        float* pc = &g_c[0][0][0];
        const int tc = L_ * B_ * H_;
        for (int i = cta * NTHR + tid; i < tc; i += NCTA * NTHR) pc[i] = 0.0f;
    }
    grid_sync();

    // ---- sequential recurrence ----
    for (int t = 0; t < T_; t++) {
        const int buf  = t & 1;
        const int nbuf = buf ^ 1;
        #pragma unroll 1
        for (int l = 0; l < L_; l++) {
            float a00 = __ldg(bias + l * G_ + jcol);
            float a01 = __ldg(bias + l * G_ + jcol + 1);
            float a10 = a00, a11 = a01;

            // input GEMM: x_t @ Wx[0]  or  h0_new @ Wx[1]
            if (l == 0) stage_x(x, t, sh_act);
            else        stage_h(&g_h[nbuf][0][0][0], sh_act);
            __syncthreads();
            kloop(sh_act, Wx + (size_t)l * H_ * G_, jcol, r0, a00, a01, a10, a11);
            __syncthreads();   // done reading sh_act before restage

            // recurrent GEMM: h_prev[l] @ Wh[l]
            stage_h(&g_h[buf][l][0][0], sh_act);
            __syncthreads();
            kloop(sh_act, Wh + (size_t)l * H_ * G_, jcol, r0, a00, a01, a10, a11);

            // exchange z within CTA
            sh_z[ r0      * 32 + lc    ] = a00;
            sh_z[ r0      * 32 + lc + 1] = a01;
            sh_z[(r0 + 1) * 32 + lc    ] = a10;
            sh_z[(r0 + 1) * 32 + lc + 1] = a11;
            __syncthreads();

            // gate update for owned (batch, unit)
            {
                float zi = sh_z[ub * 32 +      uui];
                float zf = sh_z[ub * 32 +  8 + uui];
                float zg = sh_z[ub * 32 + 16 + uui];
                float zo = sh_z[ub * 32 + 24 + uui];
                float cold = g_c[l][ub][gu];
                float ig = sigmoidf_(zi);
                float fg = sigmoidf_(zf);
                float gg = tanhf(zg);
                float og = sigmoidf_(zo);
                float cn = fg * cold + ig * gg;
                float hn = og * tanhf(cn);
                g_c[l][ub][gu]        = cn;
                g_h[nbuf][l][ub][gu]  = hn;
                if (l == 1)
                    out[(size_t)ub * T_ * H_ + (size_t)t * H_ + gu] = hn;  // y
            }
            grid_sync();  // publish h_new before anyone stages it
        }
    }

    // ---- final states: after t=511 the current states live in g_h[0] / g_c ----
    {
        const size_t offh = (size_t)B_ * T_ * H_;
        const size_t offc = offh + (size_t)L_ * B_ * H_;
        #pragma unroll
        for (int l = 0; l < L_; l++) {
            out[offh + ((size_t)l * B_ + ub) * H_ + gu] = g_h[0][l][ub][gu];
            out[offc + ((size_t)l * B_ + ub) * H_ + gu] = g_c[l][ub][gu];
        }
    }
}

extern "C" void kernel_launch(void* const* d_in, const int* in_sizes, int n_in,
                              void* d_out, int out_size) {
    const float* x    = (const float*)d_in[0];   // [B,T,H]
    const float* Wx   = (const float*)d_in[1];   // [L,H,4H]
    const float* Wh   = (const float*)d_in[2];   // [L,H,4H]
    const float* bias = (const float*)d_in[3];   // [L,4H]
    float* out = (float*)d_out;

    cudaFuncSetAttribute(lstm_persistent_kernel,
                         cudaFuncAttributeMaxDynamicSharedMemorySize, SMEM_BYTES);
    lstm_persistent_kernel<<<NCTA, NTHR, SMEM_BYTES>>>(x, Wx, Wh, bias, out);
}

// round 2
// speedup vs baseline: 1.0006x; 1.0006x over previous
#include <cuda_runtime.h>

#define B_   32
#define T_   512
#define H_   1024
#define G_   4096
#define L_   2
#define NCTA 128
#define NTHR 256
#define SMEM_BYTES ((B_*H_ + B_*32) * 4)

// Persistent state (allocation-free scratch: __device__ globals)
__device__ float g_h[2][L_][B_][H_];   // [buf][layer][b][u]
__device__ float g_c[L_][B_][H_];      // [layer][b][u]
__device__ unsigned g_bar_count = 0;
__device__ unsigned g_bar_gen   = 0;

__device__ __forceinline__ float sigmoidf_(float v) {
    return 1.0f / (1.0f + __expf(-v));
}

// Sense-free generation barrier: self-restoring across graph replays.
__device__ __forceinline__ void grid_sync() {
    __threadfence();          // make this CTA's global writes visible
    __syncthreads();
    if (threadIdx.x == 0) {
        unsigned gen = atomicAdd(&g_bar_gen, 0u);
        unsigned arrived = atomicAdd(&g_bar_count, 1u);
        if (arrived == NCTA - 1) {
            atomicExch(&g_bar_count, 0u);
            __threadfence();
            atomicAdd(&g_bar_gen, 1u);
        } else {
            while (atomicAdd(&g_bar_gen, 0u) == gen) { }
        }
        __threadfence();
    }
    __syncthreads();
}

// Stage x_t [32][1024] (strided per batch row) into SMEM
__device__ __forceinline__ void stage_x(const float* __restrict__ x, int t, float* sh) {
    #pragma unroll 8
    for (int i = 0; i < (B_*H_/4)/NTHR; i++) {
        int idx = threadIdx.x + i * NTHR;      // float4 index over [32][256]
        int b   = idx >> 8;
        int k4  = idx & 255;
        const float4* src = (const float4*)(x + (size_t)b * T_ * H_ + (size_t)t * H_);
        ((float4*)sh)[idx] = __ldg(src + k4);
    }
}

// Stage contiguous [32][1024] h buffer into SMEM, bypassing L1 (cross-CTA producer)
__device__ __forceinline__ void stage_h(const float* src, float* sh) {
    const float4* s4 = (const float4*)src;
    float4* d4 = (float4*)sh;
    #pragma unroll 8
    for (int i = 0; i < (B_*H_/4)/NTHR; i++) {
        int idx = threadIdx.x + i * NTHR;
        d4[idx] = __ldcg(s4 + idx);
    }
}

// Accumulate 2x2 output tile over K=1024: acts from SMEM, weights from L2
__device__ __forceinline__ void kloop(const float* sh_act, const float* __restrict__ W,
                                      int jcol, int r0,
                                      float& a00, float& a01, float& a10, float& a11) {
    const float2* wp  = (const float2*)(W + jcol);
    const float*  pa0 = sh_act + r0 * H_;
    const float*  pa1 = pa0 + H_;
    #pragma unroll 8
    for (int k = 0; k < H_; k++) {
        float2 w = __ldg(wp);
        wp += G_ / 2;                  // advance one weight row (4096 floats)
        float x0 = pa0[k];
        float x1 = pa1[k];
        a00 += x0 * w.x;  a01 += x0 * w.y;
        a10 += x1 * w.x;  a11 += x1 * w.y;
    }
}

extern "C" __global__ void __launch_bounds__(NTHR, 1)
lstm_persistent_kernel(const float* __restrict__ x,   // [B,T,H]
                       const float* __restrict__ Wx,  // [L,H,4H]
                       const float* __restrict__ Wh,  // [L,H,4H]
                       const float* __restrict__ bias,// [L,4H]
                       float* __restrict__ out)       // y[B,T,H] ++ h_f[L,B,H] ++ c_f[L,B,H]
{
    extern __shared__ float smem[];
    float* sh_act = smem;            // 32*1024 floats
    float* sh_z   = smem + B_ * H_;  // 32*32 floats

    const int cta = blockIdx.x;
    const int tid = threadIdx.x;

    // GEMM tile mapping: CTA owns units [cta*8, cta*8+8); 32 gate-cols x 32 batch rows
    const int cp   = tid & 15;          // col pair 0..15
    const int rp   = tid >> 4;          // row pair 0..15
    const int r0   = rp * 2;
    const int lc   = cp * 2;            // local col 0..30 (even)
    const int gate = lc >> 3;           // 0..3 (i,f,g,o)
    const int uu0  = lc & 7;
    const int u0   = cta * 8;
    const int jcol = gate * H_ + u0 + uu0;   // global gate column (pair: jcol, jcol+1)

    // Elementwise-update mapping: thread = (batch, unit)
    const int ub  = tid >> 3;   // 0..31
    const int uui = tid & 7;    // 0..7
    const int gu  = u0 + uui;   // owned hidden unit

    // ---- init state to zero (re-done every launch: deterministic) ----
    {
        float* ph = &g_h[0][0][0][0];
        const int th = 2 * L_ * B_ * H_;
        for (int i = cta * NTHR + tid; i < th; i += NCTA * NTHR) ph[i] = 0.0f;
        float* pc = &g_c[0][0][0];
        const int tc = L_ * B_ * H_;
        for (int i = cta * NTHR + tid; i < tc; i += NCTA * NTHR) pc[i] = 0.0f;
    }
    grid_sync();

    // ---- sequential recurrence ----
    for (int t = 0; t < T_; t++) {
        const int buf  = t & 1;
        const int nbuf = buf ^ 1;
        #pragma unroll 1
        for (int l = 0; l < L_; l++) {
            float a00 = __ldg(bias + l * G_ + jcol);
            float a01 = __ldg(bias + l * G_ + jcol + 1);
            float a10 = a00, a11 = a01;

            // input GEMM: x_t @ Wx[0]  or  h0_new @ Wx[1]
            if (l == 0) stage_x(x, t, sh_act);
            else        stage_h(&g_h[nbuf][0][0][0], sh_act);
            __syncthreads();
            kloop(sh_act, Wx + (size_t)l * H_ * G_, jcol, r0, a00, a01, a10, a11);
            __syncthreads();   // done reading sh_act before restage

            // recurrent GEMM: h_prev[l] @ Wh[l]
            stage_h(&g_h[buf][l][0][0], sh_act);
            __syncthreads();
            kloop(sh_act, Wh + (size_t)l * H_ * G_, jcol, r0, a00, a01, a10, a11);

            // exchange z within CTA
            sh_z[ r0      * 32 + lc    ] = a00;
            sh_z[ r0      * 32 + lc + 1] = a01;
            sh_z[(r0 + 1) * 32 + lc    ] = a10;
            sh_z[(r0 + 1) * 32 + lc + 1] = a11;
            __syncthreads();

            // gate update for owned (batch, unit)
            {
                float zi = sh_z[ub * 32 +      uui];
                float zf = sh_z[ub * 32 +  8 + uui];
                float zg = sh_z[ub * 32 + 16 + uui];
                float zo = sh_z[ub * 32 + 24 + uui];
                float cold = g_c[l][ub][gu];
                float ig = sigmoidf_(zi);
                float fg = sigmoidf_(zf);
                float gg = tanhf(zg);
                float og = sigmoidf_(zo);
                float cn = fg * cold + ig * gg;
                float hn = og * tanhf(cn);
                g_c[l][ub][gu]        = cn;
                g_h[nbuf][l][ub][gu]  = hn;
                if (l == 1)
                    out[(size_t)ub * T_ * H_ + (size_t)t * H_ + gu] = hn;  // y
            }
            grid_sync();  // publish h_new before anyone stages it
        }
    }

    // ---- final states: after t=511 the current states live in g_h[0] / g_c ----
    {
        const size_t offh = (size_t)B_ * T_ * H_;
        const size_t offc = offh + (size_t)L_ * B_ * H_;
        #pragma unroll
        for (int l = 0; l < L_; l++) {
            out[offh + ((size_t)l * B_ + ub) * H_ + gu] = g_h[0][l][ub][gu];
            out[offc + ((size_t)l * B_ + ub) * H_ + gu] = g_c[l][ub][gu];
        }
    }
}

extern "C" void kernel_launch(void* const* d_in, const int* in_sizes, int n_in,
                              void* d_out, int out_size) {
    const float* x    = (const float*)d_in[0];   // [B,T,H]
    const float* Wx   = (const float*)d_in[1];   // [L,H,4H]
    const float* Wh   = (const float*)d_in[2];   // [L,H,4H]
    const float* bias = (const float*)d_in[3];   // [L,4H]
    float* out = (float*)d_out;

    cudaFuncSetAttribute(lstm_persistent_kernel,
                         cudaFuncAttributeMaxDynamicSharedMemorySize, SMEM_BYTES);
    lstm_persistent_kernel<<<NCTA, NTHR, SMEM_BYTES>>>(x, Wx, Wh, bias, out);
}

// round 3
// speedup vs baseline: 1.0008x; 1.0003x over previous
#include <cuda_runtime.h>

#define B_   32
#define T_   512
#define H_   1024
#define G_   4096
#define L_   2
#define NCTA 128
#define NTHR 256
#define SMEM_BYTES ((B_*H_ + B_*32) * 4)

// Persistent state (allocation-free scratch: __device__ globals)
__device__ float g_h[2][L_][B_][H_];   // [buf][layer][b][u]
__device__ float g_c[L_][B_][H_];      // [layer][b][u]
__device__ unsigned g_bar_count = 0;
__device__ unsigned g_bar_gen   = 0;

__device__ __forceinline__ float sigmoidf_(float v) {
    return 1.0f / (1.0f + __expf(-v));
}

// Sense-free generation barrier: self-restoring across graph replays.
__device__ __forceinline__ void grid_sync() {
    __threadfence();          // make this CTA's global writes visible
    __syncthreads();
    if (threadIdx.x == 0) {
        unsigned gen = atomicAdd(&g_bar_gen, 0u);
        unsigned arrived = atomicAdd(&g_bar_count, 1u);
        if (arrived == NCTA - 1) {
            atomicExch(&g_bar_count, 0u);
            __threadfence();
            atomicAdd(&g_bar_gen, 1u);
        } else {
            while (atomicAdd(&g_bar_gen, 0u) == gen) { }
        }
        __threadfence();
    }
    __syncthreads();
}

// Stage x_t [32][1024] (strided per batch row) into SMEM
__device__ __forceinline__ void stage_x(const float* __restrict__ x, int t, float* sh) {
    #pragma unroll 8
    for (int i = 0; i < (B_*H_/4)/NTHR; i++) {
        int idx = threadIdx.x + i * NTHR;      // float4 index over [32][256]
        int b   = idx >> 8;
        int k4  = idx & 255;
        const float4* src = (const float4*)(x + (size_t)b * T_ * H_ + (size_t)t * H_);
        ((float4*)sh)[idx] = __ldg(src + k4);
    }
}

// Stage contiguous [32][1024] h buffer into SMEM, bypassing L1 (cross-CTA producer)
__device__ __forceinline__ void stage_h(const float* src, float* sh) {
    const float4* s4 = (const float4*)src;
    float4* d4 = (float4*)sh;
    #pragma unroll 8
    for (int i = 0; i < (B_*H_/4)/NTHR; i++) {
        int idx = threadIdx.x + i * NTHR;
        d4[idx] = __ldcg(s4 + idx);
    }
}

// Accumulate 2x2 output tile over K=1024: acts from SMEM, weights from L2
__device__ __forceinline__ void kloop(const float* sh_act, const float* __restrict__ W,
                                      int jcol, int r0,
                                      float& a00, float& a01, float& a10, float& a11) {
    const float2* wp  = (const float2*)(W + jcol);
    const float*  pa0 = sh_act + r0 * H_;
    const float*  pa1 = pa0 + H_;
    #pragma unroll 8
    for (int k = 0; k < H_; k++) {
        float2 w = __ldg(wp);
        wp += G_ / 2;                  // advance one weight row (4096 floats)
        float x0 = pa0[k];
        float x1 = pa1[k];
        a00 += x0 * w.x;  a01 += x0 * w.y;
        a10 += x1 * w.x;  a11 += x1 * w.y;
    }
}

extern "C" __global__ void __launch_bounds__(NTHR, 1)
lstm_persistent_kernel(const float* __restrict__ x,   // [B,T,H]
                       const float* __restrict__ Wx,  // [L,H,4H]
                       const float* __restrict__ Wh,  // [L,H,4H]
                       const float* __restrict__ bias,// [L,4H]
                       float* __restrict__ out)       // y[B,T,H] ++ h_f[L,B,H] ++ c_f[L,B,H]
{
    extern __shared__ float smem[];
    float* sh_act = smem;            // 32*1024 floats
    float* sh_z   = smem + B_ * H_;  // 32*32 floats

    const int cta = blockIdx.x;
    const int tid = threadIdx.x;

    // GEMM tile mapping: CTA owns units [cta*8, cta*8+8); 32 gate-cols x 32 batch rows
    const int cp   = tid & 15;          // col pair 0..15
    const int rp   = tid >> 4;          // row pair 0..15
    const int r0   = rp * 2;
    const int lc   = cp * 2;            // local col 0..30 (even)
    const int gate = lc >> 3;           // 0..3 (i,f,g,o)
    const int uu0  = lc & 7;
    const int u0   = cta * 8;
    const int jcol = gate * H_ + u0 + uu0;   // global gate column (pair: jcol, jcol+1)

    // Elementwise-update mapping: thread = (batch, unit)
    const int ub  = tid >> 3;   // 0..31
    const int uui = tid & 7;    // 0..7
    const int gu  = u0 + uui;   // owned hidden unit

    // ---- init state to zero (re-done every launch: deterministic) ----
    {
        float* ph = &g_h[0][0][0][0];
        const int th = 2 * L_ * B_ * H_;
        for (int i = cta * NTHR + tid; i < th; i += NCTA * NTHR) ph[i] = 0.0f;
        float* pc = &g_c[0][0][0];
        const int tc = L_ * B_ * H_;
        for (int i = cta * NTHR + tid; i < tc; i += NCTA * NTHR) pc[i] = 0.0f;
    }
    grid_sync();

    // ---- sequential recurrence ----
    for (int t = 0; t < T_; t++) {
        const int buf  = t & 1;
        const int nbuf = buf ^ 1;
        #pragma unroll 1
        for (int l = 0; l < L_; l++) {
            float a00 = __ldg(bias + l * G_ + jcol);
            float a01 = __ldg(bias + l * G_ + jcol + 1);
            float a10 = a00, a11 = a01;

            // input GEMM: x_t @ Wx[0]  or  h0_new @ Wx[1]
            if (l == 0) stage_x(x, t, sh_act);
            else        stage_h(&g_h[nbuf][0][0][0], sh_act);
            __syncthreads();
            kloop(sh_act, Wx + (size_t)l * H_ * G_, jcol, r0, a00, a01, a10, a11);
            __syncthreads();   // done reading sh_act before restage

            // recurrent GEMM: h_prev[l] @ Wh[l]
            stage_h(&g_h[buf][l][0][0], sh_act);
            __syncthreads();
            kloop(sh_act, Wh + (size_t)l * H_ * G_, jcol, r0, a00, a01, a10, a11);

            // exchange z within CTA
            sh_z[ r0      * 32 + lc    ] = a00;
            sh_z[ r0      * 32 + lc + 1] = a01;
            sh_z[(r0 + 1) * 32 + lc    ] = a10;
            sh_z[(r0 + 1) * 32 + lc + 1] = a11;
            __syncthreads();

            // gate update for owned (batch, unit)
            {
                float zi = sh_z[ub * 32 +      uui];
                float zf = sh_z[ub * 32 +  8 + uui];
                float zg = sh_z[ub * 32 + 16 + uui];
                float zo = sh_z[ub * 32 + 24 + uui];
                float cold = g_c[l][ub][gu];
                float ig = sigmoidf_(zi);
                float fg = sigmoidf_(zf);
                float gg = tanhf(zg);
                float og = sigmoidf_(zo);
                float cn = fg * cold + ig * gg;
                float hn = og * tanhf(cn);
                g_c[l][ub][gu]        = cn;
                g_h[nbuf][l][ub][gu]  = hn;
                if (l == 1)
                    out[(size_t)ub * T_ * H_ + (size_t)t * H_ + gu] = hn;  // y
            }
            grid_sync();  // publish h_new before anyone stages it
        }
    }

    // ---- final states: after t=511 the current states live in g_h[0] / g_c ----
    {
        const size_t offh = (size_t)B_ * T_ * H_;
        const size_t offc = offh + (size_t)L_ * B_ * H_;
        #pragma unroll
        for (int l = 0; l < L_; l++) {
            out[offh + ((size_t)l * B_ + ub) * H_ + gu] = g_h[0][l][ub][gu];
            out[offc + ((size_t)l * B_ + ub) * H_ + gu] = g_c[l][ub][gu];
        }
    }
}

extern "C" void kernel_launch(void* const* d_in, const int* in_sizes, int n_in,
                              void* d_out, int out_size) {
    const float* x    = (const float*)d_in[0];   // [B,T,H]
    const float* Wx   = (const float*)d_in[1];   // [L,H,4H]
    const float* Wh   = (const float*)d_in[2];   // [L,H,4H]
    const float* bias = (const float*)d_in[3];   // [L,4H]
    float* out = (float*)d_out;

    cudaFuncSetAttribute(lstm_persistent_kernel,
                         cudaFuncAttributeMaxDynamicSharedMemorySize, SMEM_BYTES);
    lstm_persistent_kernel<<<NCTA, NTHR, SMEM_BYTES>>>(x, Wx, Wh, bias, out);
}

// round 8
// speedup vs baseline: 3.3903x; 3.3875x over previous
#include <cuda_runtime.h>
#include <cuda_bf16.h>
#include <cstdint>

#define B_ 32
#define T_ 512
#define H_ 1024
#define G_ 4096
#define NCTA 32
#define NTHR 128
#define OFFH ((size_t)B_*T_*H_)
#define OFFC (OFFH + (size_t)2*B_*H_)
#define STG_BYTES 81920u
#define ZOFF 163840
#define COFF 180736
#define BIASOFF 189184
#define DYNSM 191232

// W images: [l2][mat2][part2][cta32][chunk8] blocks of 32KB ([k128][16 gran][16B], swizzled)
__device__ __align__(1024) unsigned char g_W[67108864];
// x images per t: [64 rows (hi0-31, lo32-63)][2048 B], swizzled
__device__ __align__(1024) unsigned char g_X[67108864];
// h images: [l*2+buf][64 rows][2048 B]
__device__ __align__(1024) unsigned char g_Hb[524288];
__device__ unsigned g_bar_count = 0;
__device__ unsigned g_bar_gen = 0;

__device__ __forceinline__ uint32_t smem_u32_of(const void* p) {
    uint32_t a;
    asm("{ .reg .u64 t; cvta.to.shared.u64 t, %1; cvt.u32.u64 %0, t; }" : "=r"(a) : "l"(p));
    return a;
}
__device__ __forceinline__ void cp16(uint32_t d, const void* s) {
    asm volatile("cp.async.cg.shared.global [%0], [%1], 16;" :: "r"(d), "l"(s));
}
#define CP_COMMIT() asm volatile("cp.async.commit_group;" ::: "memory")
#define CP_WAIT1() asm volatile("cp.async.wait_group 1;" ::: "memory")
#define CP_WAIT0() asm volatile("cp.async.wait_group 0;" ::: "memory")
#define LDSM4(r, a) asm volatile("ldmatrix.sync.aligned.m8n8.x4.shared.b16 {%0,%1,%2,%3}, [%4];" \
    : "=r"((r)[0]),"=r"((r)[1]),"=r"((r)[2]),"=r"((r)[3]) : "r"(a))
#define LDSM4T(r, a) asm volatile("ldmatrix.sync.aligned.m8n8.x4.trans.shared.b16 {%0,%1,%2,%3}, [%4];" \
    : "=r"((r)[0]),"=r"((r)[1]),"=r"((r)[2]),"=r"((r)[3]) : "r"(a))
#define MMA(d, a, b0, b1) asm volatile( \
    "mma.sync.aligned.m16n8k16.row.col.f32.bf16.bf16.f32 {%0,%1,%2,%3},{%4,%5,%6,%7},{%8,%9},{%0,%1,%2,%3};" \
    : "+f"((d)[0]),"+f"((d)[1]),"+f"((d)[2]),"+f"((d)[3]) \
    : "r"((a)[0]),"r"((a)[1]),"r"((a)[2]),"r"((a)[3]), "r"(b0),"r"(b1))

__device__ __forceinline__ float sigmoidf_(float v) { return 1.0f / (1.0f + __expf(-v)); }

__device__ __forceinline__ void grid_sync() {
    __threadfence();
    __syncthreads();
    if (threadIdx.x == 0) {
        unsigned gen = atomicAdd(&g_bar_gen, 0u);
        unsigned arrived = atomicAdd(&g_bar_count, 1u);
        if (arrived == NCTA - 1) {
            atomicExch(&g_bar_count, 0u);
            __threadfence();
            atomicAdd(&g_bar_gen, 1u);
        } else {
            while (atomicAdd(&g_bar_gen, 0u) == gen) { __nanosleep(32); }
        }
        __threadfence();
    }
    __syncthreads();
}

// row image byte offset with baked XOR-low3 swizzle (pitch 2048 B, k in 0..1023 bf16)
__device__ __forceinline__ uint32_t actoff(int r, int k) {
    int g = k >> 3;
    int gp = (g & ~7) | ((g ^ (r & 7)) & 7);
    return (uint32_t)(r * 2048 + gp * 16 + (k & 7) * 2);
}

// ---- prep: weights -> per-CTA k-major swizzled bf16 hi/lo blocks ----
__global__ void prep_w(const float* __restrict__ Wx, const float* __restrict__ Wh) {
    int lm = blockIdx.z, l = lm >> 1, mat = lm & 1;
    const float* W = (mat ? Wh : Wx) + (size_t)l * H_ * G_;
    int col = blockIdx.x * 256 + threadIdx.x;           // 0..4095
    int cta = (col & 1023) >> 5, uu = col & 31, gate = col >> 10;
    int m = gate * 32 + uu;                              // 0..127 within CTA
    int g8 = m >> 3;
    size_t bhi = (size_t)((((l*2+mat)*2 + 0)*32 + cta)*8) << 15;
    size_t blo = (size_t)((((l*2+mat)*2 + 1)*32 + cta)*8) << 15;
    #pragma unroll
    for (int i = 0; i < 8; i++) {
        int k = blockIdx.y * 8 + i;                      // 0..1023
        float f = W[(size_t)k * G_ + col];
        __nv_bfloat16 hi = __float2bfloat16(f);
        __nv_bfloat16 lo = __float2bfloat16(f - __bfloat162float(hi));
        int cc = k >> 7, krow = k & 127;
        int gp = (g8 & 8) | ((g8 ^ (krow & 7)) & 7);
        size_t off = ((size_t)cc << 15) + krow * 256 + gp * 16 + (m & 7) * 2;
        *(__nv_bfloat16*)(g_W + bhi + off) = hi;
        *(__nv_bfloat16*)(g_W + blo + off) = lo;
    }
}

__global__ void prep_x(const float* __restrict__ x) {
    int t = blockIdx.y;
    int g = blockIdx.x * 256 + threadIdx.x;   // 8192 per t
    int b = g >> 8, kq = (g & 255) * 4;
    float4 v = *(const float4*)(x + ((size_t)b * T_ + t) * H_ + kq);
    float f[4] = {v.x, v.y, v.z, v.w};
    __align__(8) __nv_bfloat16 hv[4], lv[4];
    #pragma unroll
    for (int r = 0; r < 4; r++) {
        hv[r] = __float2bfloat16(f[r]);
        lv[r] = __float2bfloat16(f[r] - __bfloat162float(hv[r]));
    }
    unsigned char* img = g_X + ((size_t)t << 17);
    *(uint2*)(img + actoff(b, kq)) = *(uint2*)hv;
    *(uint2*)(img + actoff(b + 32, kq)) = *(uint2*)lv;
}

// ---- main persistent kernel ----
extern "C" __global__ void __launch_bounds__(NTHR, 1)
lstm_mma(const float* __restrict__ bias, float* __restrict__ out) {
    extern __shared__ unsigned char smraw[];
    unsigned char* sm = (unsigned char*)(((uintptr_t)smraw + 1023) & ~(uintptr_t)1023);
    const int tid = threadIdx.x, cta = blockIdx.x;
    const int wid = tid >> 5, lane = tid & 31;
    uint32_t smb = smem_u32_of(sm);
    float* shz = (float*)(sm + ZOFF);    // [32][132]
    float* shc = (float*)(sm + COFF);    // [2*32][33]
    float* shb = (float*)(sm + BIASOFF); // [2][128]

    for (int i = tid; i < 256; i += NTHR) {
        int l = i >> 7, m = i & 127;
        shb[i] = bias[l * G_ + (m >> 5) * 1024 + cta * 32 + (m & 31)];
    }
    for (int i = tid; i < 2 * 32 * 33; i += NTHR) shc[i] = 0.f;
    for (int i = cta * NTHR + tid; i < 32768; i += NCTA * NTHR)
        ((uint4*)g_Hb)[i] = make_uint4(0, 0, 0, 0);
    grid_sync();

    // per-thread ldmatrix lane addressing
    const int rowL = lane & 15, ksel = (lane >> 4) & 1;
    const int krowL = lane & 15, gsel = (lane >> 4) & 1;
    const int gc0 = wid * 4 + gsel, gc1 = wid * 4 + 2 + gsel;
    const int eg = lane >> 2, etc = lane & 3;
    const int u = tid & 31, bb0 = (tid >> 5) * 8;
    const int un = cta * 32 + u, g8h = un >> 3;

    for (int t = 0; t < T_; t++) {
        const int buf = t & 1, nbuf = buf ^ 1;
        for (int l = 0; l < 2; l++) {
            const unsigned char* img0 = (l == 0) ? (g_X + ((size_t)t << 17))
                                                 : (g_Hb + ((size_t)(0 * 2 + nbuf) << 17));
            const unsigned char* img1 = g_Hb + ((size_t)(l * 2 + buf) << 17);

            float acc1[4][4][4], acc2[2][4][4];
            #pragma unroll
            for (int a = 0; a < 4; a++)
                #pragma unroll
                for (int b = 0; b < 4; b++)
                    #pragma unroll
                    for (int k = 0; k < 4; k++) {
                        acc1[a][b][k] = 0.f;
                        if (a < 2) acc2[a][b][k] = 0.f;
                    }

            // -------- issue helper (inlined twice via lambda) --------
            auto issue = [&](int chunk) {
                int mat = chunk >> 3, cc = chunk & 7;
                const unsigned char* img = mat ? img1 : img0;
                uint32_t stg = smb + (uint32_t)(chunk & 1) * STG_BYTES;
                size_t wbh = (size_t)(((((l*2+mat)*2 + 0)*32 + cta)*8 + cc)) << 15;
                size_t wbl = (size_t)(((((l*2+mat)*2 + 1)*32 + cta)*8 + cc)) << 15;
                #pragma unroll
                for (int j = 0; j < 40; j++) {
                    int gidx = tid + j * NTHR;
                    if (gidx < 4096) {
                        int part = gidx >> 11;
                        uint32_t off = (uint32_t)(gidx & 2047) << 4;
                        const unsigned char* src = g_W + (part ? wbl : wbh) + off;
                        cp16(stg + (uint32_t)part * 32768u + off, src);
                    } else {
                        int a = gidx - 4096;
                        int r = a >> 4, gi = a & 15;
                        cp16(stg + 65536u + (uint32_t)(r * 256 + gi * 16),
                             img + r * 2048 + cc * 256 + gi * 16);
                    }
                }
                CP_COMMIT();
            };

            issue(0); issue(1);

            for (int c = 0; c < 16; c++) {
                if (c < 15) { CP_WAIT1(); } else { CP_WAIT0(); }
                __syncthreads();
                uint32_t stg = smb + (uint32_t)(c & 1) * STG_BYTES;
                uint32_t actb = stg + 65536u;
                #pragma unroll
                for (int kk = 0; kk < 128; kk += 16) {
                    uint32_t a[4][4], bh[2][4], bl[2][4];
                    int gA = (kk >> 3) + ksel;
                    #pragma unroll
                    for (int mt = 0; mt < 4; mt++) {
                        int row = mt * 16 + rowL;
                        uint32_t gp = (uint32_t)((gA & 8) | ((gA ^ (row & 7)) & 7));
                        LDSM4(a[mt], actb + (uint32_t)row * 256u + (gp << 4));
                    }
                    int kr = kk + krowL, krx = kr & 7;
                    {
                        uint32_t gp0 = (uint32_t)((gc0 & 8) | ((gc0 ^ krx) & 7));
                        uint32_t gp1 = (uint32_t)((gc1 & 8) | ((gc1 ^ krx) & 7));
                        uint32_t rb = stg + (uint32_t)kr * 256u;
                        LDSM4T(bh[0], rb + (gp0 << 4));
                        LDSM4T(bh[1], rb + (gp1 << 4));
                        LDSM4T(bl[0], rb + 32768u + (gp0 << 4));
                        LDSM4T(bl[1], rb + 32768u + (gp1 << 4));
                    }
                    #pragma unroll
                    for (int mt = 0; mt < 4; mt++)
                        #pragma unroll
                        for (int nt = 0; nt < 4; nt++)
                            MMA(acc1[mt][nt], a[mt], bh[nt >> 1][(nt & 1) * 2], bh[nt >> 1][(nt & 1) * 2 + 1]);
                    #pragma unroll
                    for (int mt = 0; mt < 2; mt++)
                        #pragma unroll
                        for (int nt = 0; nt < 4; nt++)
                            MMA(acc2[mt][nt], a[mt], bl[nt >> 1][(nt & 1) * 2], bl[nt >> 1][(nt & 1) * 2 + 1]);
                }
                __syncthreads();
                if (c < 14) issue(c + 2);
            }

            // -------- epilogue: combine 3 terms + bias into shz[b][col] --------
            #pragma unroll
            for (int mt = 0; mt < 2; mt++)
                #pragma unroll
                for (int nt = 0; nt < 4; nt++)
                    #pragma unroll
                    for (int k = 0; k < 4; k++) {
                        float v = acc1[mt][nt][k] + acc1[mt + 2][nt][k] + acc2[mt][nt][k];
                        int b = mt * 16 + eg + ((k >> 1) << 3);
                        int col = wid * 32 + nt * 8 + etc * 2 + (k & 1);
                        shz[b * 132 + col] = v + shb[l * 128 + col];
                    }
            __syncthreads();

            // -------- gate update + h publish --------
            {
                unsigned char* hdst = g_Hb + ((size_t)(l * 2 + nbuf) << 17);
                #pragma unroll
                for (int bb = 0; bb < 8; bb++) {
                    int b = bb0 + bb;
                    float zi = shz[b * 132 + u];
                    float zf = shz[b * 132 + 32 + u];
                    float zg = shz[b * 132 + 64 + u];
                    float zo = shz[b * 132 + 96 + u];
                    float* cp_ = &shc[(l * 32 + b) * 33 + u];
                    float cold = *cp_;
                    float ig = sigmoidf_(zi), fg = sigmoidf_(zf);
                    float gg = tanhf(zg), og = sigmoidf_(zo);
                    float cn = fg * cold + ig * gg;
                    float hn = og * tanhf(cn);
                    *cp_ = cn;
                    __nv_bfloat16 hh = __float2bfloat16(hn);
                    __nv_bfloat16 hl = __float2bfloat16(hn - __bfloat162float(hh));
                    int gp = (g8h & ~7) | ((g8h ^ (b & 7)) & 7);
                    uint32_t off = (uint32_t)(b * 2048 + gp * 16 + (un & 7) * 2);
                    *(__nv_bfloat16*)(hdst + off) = hh;
                    *(__nv_bfloat16*)(hdst + off + 65536u) = hl;
                    if (l == 1) out[(size_t)b * T_ * H_ + (size_t)t * H_ + un] = hn;
                    if (t == T_ - 1) {
                        out[OFFH + (size_t)(l * B_ + b) * H_ + un] = hn;
                        out[OFFC + (size_t)(l * B_ + b) * H_ + un] = cn;
                    }
                }
            }
            grid_sync();
        }
    }
}

extern "C" void kernel_launch(void* const* d_in, const int* in_sizes, int n_in,
                              void* d_out, int out_size) {
    const float* x = (const float*)d_in[0];
    const float* Wx = (const float*)d_in[1];
    const float* Wh = (const float*)d_in[2];
    const float* bias = (const float*)d_in[3];
    float* out = (float*)d_out;
    prep_w<<<dim3(16, 128, 4), 256>>>(Wx, Wh);
    prep_x<<<dim3(32, 512), 256>>>(x);
    cudaFuncSetAttribute(lstm_mma, cudaFuncAttributeMaxDynamicSharedMemorySize, DYNSM);
    lstm_mma<<<NCTA, NTHR, DYNSM>>>(bias, out);
}

// round 11
// speedup vs baseline: 6.5848x; 1.9422x over previous
#include <cuda_runtime.h>
#include <cuda_bf16.h>
#include <cstdint>

#define B_ 32
#define T_ 512
#define H_ 1024
#define G_ 4096
#define NCTA 128
#define NTHR 128
#define OFFH ((size_t)B_*T_*H_)
#define OFFC (OFFH + (size_t)2*B_*H_)
#define STG_BYTES 32768u
#define ZOFF 131072
#define COFF 135680
#define BIASOFF 137984
#define DYNSM 139264

// W blocks: [l2][mat2][part2][cta128][chunk8] of 8KB = [k128][4 gran][16B] (gran = gate, XOR-swizzled)
#define WB(l,mat,part,cta,cc) ((size_t)(((((l)*2+(mat))*2+(part))*128 + (cta))*8 + (cc)) << 13)
__device__ __align__(1024) unsigned char g_W[67108864];
// x images per t: [64 rows (hi 0-31, lo 32-63)][2048 B], XOR-swizzled granules
__device__ __align__(1024) unsigned char g_X[67108864];
// h images: [l*2+buf][64 rows][2048 B]
__device__ __align__(1024) unsigned char g_Hb[524288];
__device__ unsigned g_bar_count = 0;
__device__ unsigned g_bar_gen = 0;

__device__ __forceinline__ uint32_t smem_u32_of(const void* p) {
    uint32_t a;
    asm("{ .reg .u64 t; cvta.to.shared.u64 t, %1; cvt.u32.u64 %0, t; }" : "=r"(a) : "l"(p));
    return a;
}
__device__ __forceinline__ void cp16(uint32_t d, const void* s) {
    asm volatile("cp.async.cg.shared.global [%0], [%1], 16;" :: "r"(d), "l"(s));
}
#define CP_COMMIT() asm volatile("cp.async.commit_group;" ::: "memory")
#define CP_WAIT2() asm volatile("cp.async.wait_group 2;" ::: "memory")
#define CP_WAIT1() asm volatile("cp.async.wait_group 1;" ::: "memory")
#define CP_WAIT0() asm volatile("cp.async.wait_group 0;" ::: "memory")
#define LDSM4(r, a) asm volatile("ldmatrix.sync.aligned.m8n8.x4.shared.b16 {%0,%1,%2,%3}, [%4];" \
    : "=r"((r)[0]),"=r"((r)[1]),"=r"((r)[2]),"=r"((r)[3]) : "r"(a))
#define LDSM2T(r, a) asm volatile("ldmatrix.sync.aligned.m8n8.x2.trans.shared.b16 {%0,%1}, [%2];" \
    : "=r"((r)[0]),"=r"((r)[1]) : "r"(a))
#define MMA(d, a, b0, b1) asm volatile( \
    "mma.sync.aligned.m16n8k16.row.col.f32.bf16.bf16.f32 {%0,%1,%2,%3},{%4,%5,%6,%7},{%8,%9},{%0,%1,%2,%3};" \
    : "+f"((d)[0]),"+f"((d)[1]),"+f"((d)[2]),"+f"((d)[3]) \
    : "r"((a)[0]),"r"((a)[1]),"r"((a)[2]),"r"((a)[3]), "r"(b0),"r"(b1))

__device__ __forceinline__ float sigmoidf_(float v) { return 1.0f / (1.0f + __expf(-v)); }

__device__ __forceinline__ void grid_sync() {
    __threadfence();
    __syncthreads();
    if (threadIdx.x == 0) {
        unsigned gen = atomicAdd(&g_bar_gen, 0u);
        unsigned arrived = atomicAdd(&g_bar_count, 1u);
        if (arrived == NCTA - 1) {
            atomicExch(&g_bar_count, 0u);
            __threadfence();
            atomicAdd(&g_bar_gen, 1u);
        } else {
            while (atomicAdd(&g_bar_gen, 0u) == gen) { __nanosleep(16); }
        }
        __threadfence();
    }
    __syncthreads();
}

// act image byte offset (pitch 2048 B, k in bf16 units), XOR-low3 granule swizzle
__device__ __forceinline__ uint32_t actoff(int r, int k) {
    int g = k >> 3;
    int gp = (g & ~7) | ((g ^ (r & 7)) & 7);
    return (uint32_t)(r * 2048 + gp * 16 + (k & 7) * 2);
}

// ---- prep: weights -> per-CTA (32-col) k-major swizzled bf16 hi/lo blocks ----
__global__ void prep_w(const float* __restrict__ Wx, const float* __restrict__ Wh) {
    int lm = blockIdx.z, l = lm >> 1, mat = lm & 1;
    const float* W = (mat ? Wh : Wx) + (size_t)l * H_ * G_;
    int col = blockIdx.x * 256 + threadIdx.x;           // 0..4095
    int cta = (col & 1023) >> 3, uu = col & 7, gate = col >> 10;
    size_t bhi = WB(l, mat, 0, cta, 0);
    size_t blo = WB(l, mat, 1, cta, 0);
    #pragma unroll
    for (int i = 0; i < 8; i++) {
        int k = blockIdx.y * 8 + i;                      // 0..1023
        float f = W[(size_t)k * G_ + col];
        __nv_bfloat16 hi = __float2bfloat16(f);
        __nv_bfloat16 lo = __float2bfloat16(f - __bfloat162float(hi));
        int cc = k >> 7, krow = k & 127;
        int gp = gate ^ ((krow >> 1) & 3);
        size_t off = ((size_t)cc << 13) + krow * 64 + gp * 16 + uu * 2;
        *(__nv_bfloat16*)(g_W + bhi + off) = hi;
        *(__nv_bfloat16*)(g_W + blo + off) = lo;
    }
}

__global__ void prep_x(const float* __restrict__ x) {
    int t = blockIdx.y;
    int g = blockIdx.x * 256 + threadIdx.x;   // 8192 per t
    int b = g >> 8, kq = (g & 255) * 4;
    float4 v = *(const float4*)(x + ((size_t)b * T_ + t) * H_ + kq);
    float f[4] = {v.x, v.y, v.z, v.w};
    __align__(8) __nv_bfloat16 hv[4], lv[4];
    #pragma unroll
    for (int r = 0; r < 4; r++) {
        hv[r] = __float2bfloat16(f[r]);
        lv[r] = __float2bfloat16(f[r] - __bfloat162float(hv[r]));
    }
    unsigned char* img = g_X + ((size_t)t << 17);
    *(uint2*)(img + actoff(b, kq)) = *(uint2*)hv;
    *(uint2*)(img + actoff(b + 32, kq)) = *(uint2*)lv;
}

// ---- main persistent kernel: 128 CTAs, CTA owns 8 hidden units (32 gate-cols) ----
extern "C" __global__ void __launch_bounds__(NTHR, 1)
lstm_mma(const float* __restrict__ bias, float* __restrict__ out) {
    extern __shared__ unsigned char smraw[];
    unsigned char* sm = (unsigned char*)(((uintptr_t)smraw + 1023) & ~(uintptr_t)1023);
    const int tid = threadIdx.x, cta = blockIdx.x;
    const int wid = tid >> 5, lane = tid & 31;
    uint32_t smb = smem_u32_of(sm);
    float* shz = (float*)(sm + ZOFF);    // [32][36]
    float* shc = (float*)(sm + COFF);    // [2*32][9]
    float* shb = (float*)(sm + BIASOFF); // [2][32]

    for (int i = tid; i < 64; i += NTHR) {
        int l = i >> 5, m = i & 31;
        shb[i] = bias[l * G_ + (m >> 3) * 1024 + cta * 8 + (m & 7)];
    }
    for (int i = tid; i < 2 * 32 * 9; i += NTHR) shc[i] = 0.f;
    for (int i = cta * NTHR + tid; i < 32768; i += NCTA * NTHR)
        ((uint4*)g_Hb)[i] = make_uint4(0, 0, 0, 0);
    grid_sync();

    // ldmatrix lane addressing
    const int rowL = lane & 15, ksel = (lane >> 4) & 1;   // A loads
    const int krL = lane & 15;                            // B loads (lanes 0-15 meaningful)
    const int eg = lane >> 2, etc = lane & 3;             // epilogue fragment map
    const int u = tid & 7, bp = tid >> 3;                 // elementwise map
    const int un = cta * 8 + u;

    for (int t = 0; t < T_; t++) {
        const int buf = t & 1, nbuf = buf ^ 1;
        for (int l = 0; l < 2; l++) {
            const unsigned char* img0 = (l == 0) ? (g_X + ((size_t)t << 17))
                                                 : (g_Hb + ((size_t)nbuf << 17));
            const unsigned char* img1 = g_Hb + ((size_t)(l * 2 + buf) << 17);

            float acc1[4][4], acc2[2][4];
            #pragma unroll
            for (int a = 0; a < 4; a++)
                #pragma unroll
                for (int k = 0; k < 4; k++) { acc1[a][k] = 0.f; if (a < 2) acc2[a][k] = 0.f; }

            auto issue = [&](int chunk) {
                int mat = chunk >> 3, cc = chunk & 7;
                const unsigned char* img = mat ? img1 : img0;
                uint32_t stg = smb + (uint32_t)(chunk & 3) * STG_BYTES;
                size_t wbh = WB(l, mat, 0, cta, cc);
                size_t wbl = WB(l, mat, 1, cta, cc);
                #pragma unroll
                for (int j = 0; j < 16; j++) {
                    int gidx = tid + j * NTHR;            // 0..2047
                    if (gidx < 512) {
                        uint32_t off = (uint32_t)gidx << 4;
                        cp16(stg + off, g_W + wbh + off);
                    } else if (gidx < 1024) {
                        uint32_t off = (uint32_t)(gidx - 512) << 4;
                        cp16(stg + 8192u + off, g_W + wbl + off);
                    } else {
                        int a = gidx - 1024;
                        int r = a >> 4, gi = a & 15;
                        cp16(stg + 16384u + (uint32_t)(r * 256 + gi * 16),
                             img + r * 2048 + cc * 256 + gi * 16);
                    }
                }
                CP_COMMIT();
            };

            issue(0); issue(1); issue(2);

            for (int c = 0; c < 16; c++) {
                if (c <= 13) { CP_WAIT2(); } else if (c == 14) { CP_WAIT1(); } else { CP_WAIT0(); }
                __syncthreads();
                uint32_t stg = smb + (uint32_t)(c & 3) * STG_BYTES;
                uint32_t actb = stg + 16384u;
                #pragma unroll
                for (int kk = 0; kk < 128; kk += 16) {
                    uint32_t a[4][4], bh[2], bl[2];
                    int gA = (kk >> 3) + ksel;
                    #pragma unroll
                    for (int mt = 0; mt < 4; mt++) {
                        int row = mt * 16 + rowL;
                        uint32_t gp = (uint32_t)((gA & 8) | ((gA ^ (row & 7)) & 7));
                        LDSM4(a[mt], actb + (uint32_t)row * 256u + (gp << 4));
                    }
                    {
                        int kr = kk + krL;
                        uint32_t gp = (uint32_t)(wid ^ ((kr >> 1) & 3));
                        uint32_t rb = stg + (uint32_t)kr * 64u + (gp << 4);
                        LDSM2T(bh, rb);
                        LDSM2T(bl, rb + 8192u);
                    }
                    #pragma unroll
                    for (int mt = 0; mt < 4; mt++)
                        MMA(acc1[mt], a[mt], bh[0], bh[1]);
                    #pragma unroll
                    for (int mt = 0; mt < 2; mt++)
                        MMA(acc2[mt], a[mt], bl[0], bl[1]);
                }
                __syncthreads();
                if (c < 13) issue(c + 3);
            }

            // epilogue: z = Whi*ahi + Whi*alo + Wlo*ahi + bias
            #pragma unroll
            for (int mt = 0; mt < 2; mt++)
                #pragma unroll
                for (int k = 0; k < 4; k++) {
                    float v = acc1[mt][k] + acc1[mt + 2][k] + acc2[mt][k];
                    int b = mt * 16 + eg + ((k >> 1) << 3);
                    int col = wid * 8 + etc * 2 + (k & 1);
                    shz[b * 36 + col] = v + shb[l * 32 + col];
                }
            __syncthreads();

            // gate update + h publish (each thread: unit u, 2 batches)
            {
                unsigned char* hdst = g_Hb + ((size_t)(l * 2 + nbuf) << 17);
                #pragma unroll
                for (int j = 0; j < 2; j++) {
                    int b = bp * 2 + j;
                    float zi = shz[b * 36 + u];
                    float zf = shz[b * 36 + 8 + u];
                    float zg = shz[b * 36 + 16 + u];
                    float zo = shz[b * 36 + 24 + u];
                    float* cp_ = &shc[(l * 32 + b) * 9 + u];
                    float cold = *cp_;
                    float ig = sigmoidf_(zi), fg = sigmoidf_(zf);
                    float gg = tanhf(zg), og = sigmoidf_(zo);
                    float cn = fg * cold + ig * gg;
                    float hn = og * tanhf(cn);
                    *cp_ = cn;
                    __nv_bfloat16 hh = __float2bfloat16(hn);
                    __nv_bfloat16 hl = __float2bfloat16(hn - __bfloat162float(hh));
                    *(__nv_bfloat16*)(hdst + actoff(b, un)) = hh;
                    *(__nv_bfloat16*)(hdst + actoff(b + 32, un)) = hl;
                    if (l == 1) out[(size_t)b * T_ * H_ + (size_t)t * H_ + un] = hn;
                    if (t == T_ - 1) {
                        out[OFFH + (size_t)(l * B_ + b) * H_ + un] = hn;
                        out[OFFC + (size_t)(l * B_ + b) * H_ + un] = cn;
                    }
                }
            }
            grid_sync();
        }
    }
}

extern "C" void kernel_launch(void* const* d_in, const int* in_sizes, int n_in,
                              void* d_out, int out_size) {
    const float* x = (const float*)d_in[0];
    const float* Wx = (const float*)d_in[1];
    const float* Wh = (const float*)d_in[2];
    const float* bias = (const float*)d_in[3];
    float* out = (float*)d_out;
    prep_w<<<dim3(16, 128, 4), 256>>>(Wx, Wh);
    prep_x<<<dim3(32, 512), 256>>>(x);
    cudaFuncSetAttribute(lstm_mma, cudaFuncAttributeMaxDynamicSharedMemorySize, DYNSM);
    lstm_mma<<<NCTA, NTHR, DYNSM>>>(bias, out);
}

// round 12
// speedup vs baseline: 7.7608x; 1.1786x over previous
#include <cuda_runtime.h>
#include <cuda_bf16.h>
#include <cstdint>

#define B_ 32
#define T_ 512
#define H_ 1024
#define G_ 4096
#define NCTA 128
#define NTHR 256
#define OFFH ((size_t)B_*T_*H_)
#define OFFC (OFFH + (size_t)2*B_*H_)
#define STG_BYTES 32768u
#define WGSTRIDE 98304u
#define ZOFF0 196608
#define ZOFF1 201216
#define COFF 205824
#define BIASOFF 208128
#define DYNSM 212992

// W blocks: [l2][mat2][part2][cta128][chunk8] of 8KB = [k128][4 gran][16B] (gran = gate, XOR-swizzled)
#define WB(l,mat,part,cta,cc) ((size_t)(((((l)*2+(mat))*2+(part))*128 + (cta))*8 + (cc)) << 13)
__device__ __align__(1024) unsigned char g_W[67108864];
// x images per t: [64 rows (hi 0-31, lo 32-63)][2048 B], XOR-swizzled granules
__device__ __align__(1024) unsigned char g_X[67108864];
// h images: [l*2+buf][64 rows][2048 B]
__device__ __align__(1024) unsigned char g_Hb[524288];
__device__ unsigned g_bar_count = 0;
__device__ unsigned g_bar_gen = 0;

__device__ __forceinline__ uint32_t smem_u32_of(const void* p) {
    uint32_t a;
    asm("{ .reg .u64 t; cvta.to.shared.u64 t, %1; cvt.u32.u64 %0, t; }" : "=r"(a) : "l"(p));
    return a;
}
__device__ __forceinline__ void cp16(uint32_t d, const void* s) {
    asm volatile("cp.async.cg.shared.global [%0], [%1], 16;" :: "r"(d), "l"(s));
}
#define CP_COMMIT() asm volatile("cp.async.commit_group;" ::: "memory")
#define CP_WAIT2() asm volatile("cp.async.wait_group 2;" ::: "memory")
#define CP_WAIT1() asm volatile("cp.async.wait_group 1;" ::: "memory")
#define CP_WAIT0() asm volatile("cp.async.wait_group 0;" ::: "memory")
#define WG_BAR(id) asm volatile("bar.sync %0, 128;" :: "r"(id) : "memory")
#define LDSM4(r, a) asm volatile("ldmatrix.sync.aligned.m8n8.x4.shared.b16 {%0,%1,%2,%3}, [%4];" \
    : "=r"((r)[0]),"=r"((r)[1]),"=r"((r)[2]),"=r"((r)[3]) : "r"(a))
#define LDSM2T(r, a) asm volatile("ldmatrix.sync.aligned.m8n8.x2.trans.shared.b16 {%0,%1}, [%2];" \
    : "=r"((r)[0]),"=r"((r)[1]) : "r"(a))
#define MMA(d, a, b0, b1) asm volatile( \
    "mma.sync.aligned.m16n8k16.row.col.f32.bf16.bf16.f32 {%0,%1,%2,%3},{%4,%5,%6,%7},{%8,%9},{%0,%1,%2,%3};" \
    : "+f"((d)[0]),"+f"((d)[1]),"+f"((d)[2]),"+f"((d)[3]) \
    : "r"((a)[0]),"r"((a)[1]),"r"((a)[2]),"r"((a)[3]), "r"(b0),"r"(b1))

__device__ __forceinline__ float sigmoidf_(float v) { return 1.0f / (1.0f + __expf(-v)); }

__device__ __forceinline__ void grid_sync() {
    __threadfence();
    __syncthreads();
    if (threadIdx.x == 0) {
        unsigned gen = atomicAdd(&g_bar_gen, 0u);
        unsigned arrived = atomicAdd(&g_bar_count, 1u);
        if (arrived == NCTA - 1) {
            atomicExch(&g_bar_count, 0u);
            __threadfence();
            atomicAdd(&g_bar_gen, 1u);
        } else {
            while (atomicAdd(&g_bar_gen, 0u) == gen) { __nanosleep(16); }
        }
        __threadfence();
    }
    __syncthreads();
}

// act image byte offset (pitch 2048 B, k in bf16 units), XOR-low3 granule swizzle
__device__ __forceinline__ uint32_t actoff(int r, int k) {
    int g = k >> 3;
    int gp = (g & ~7) | ((g ^ (r & 7)) & 7);
    return (uint32_t)(r * 2048 + gp * 16 + (k & 7) * 2);
}

__global__ void prep_w(const float* __restrict__ Wx, const float* __restrict__ Wh) {
    int lm = blockIdx.z, l = lm >> 1, mat = lm & 1;
    const float* W = (mat ? Wh : Wx) + (size_t)l * H_ * G_;
    int col = blockIdx.x * 256 + threadIdx.x;           // 0..4095
    int cta = (col & 1023) >> 3, uu = col & 7, gate = col >> 10;
    size_t bhi = WB(l, mat, 0, cta, 0);
    size_t blo = WB(l, mat, 1, cta, 0);
    #pragma unroll
    for (int i = 0; i < 8; i++) {
        int k = blockIdx.y * 8 + i;                      // 0..1023
        float f = W[(size_t)k * G_ + col];
        __nv_bfloat16 hi = __float2bfloat16(f);
        __nv_bfloat16 lo = __float2bfloat16(f - __bfloat162float(hi));
        int cc = k >> 7, krow = k & 127;
        int gp = gate ^ ((krow >> 1) & 3);
        size_t off = ((size_t)cc << 13) + krow * 64 + gp * 16 + uu * 2;
        *(__nv_bfloat16*)(g_W + bhi + off) = hi;
        *(__nv_bfloat16*)(g_W + blo + off) = lo;
    }
}

__global__ void prep_x(const float* __restrict__ x) {
    int t = blockIdx.y;
    int g = blockIdx.x * 256 + threadIdx.x;   // 8192 per t
    int b = g >> 8, kq = (g & 255) * 4;
    float4 v = *(const float4*)(x + ((size_t)b * T_ + t) * H_ + kq);
    float f[4] = {v.x, v.y, v.z, v.w};
    __align__(8) __nv_bfloat16 hv[4], lv[4];
    #pragma unroll
    for (int r = 0; r < 4; r++) {
        hv[r] = __float2bfloat16(f[r]);
        lv[r] = __float2bfloat16(f[r] - __bfloat162float(hv[r]));
    }
    unsigned char* img = g_X + ((size_t)t << 17);
    *(uint2*)(img + actoff(b, kq)) = *(uint2*)hv;
    *(uint2*)(img + actoff(b + 32, kq)) = *(uint2*)lv;
}

// ---- main persistent kernel: 128 CTAs x 256 thr; wg0 = input GEMM, wg1 = recurrent GEMM ----
extern "C" __global__ void __launch_bounds__(NTHR, 1)
lstm_mma(const float* __restrict__ bias, float* __restrict__ out) {
    extern __shared__ unsigned char smraw[];
    unsigned char* sm = (unsigned char*)(((uintptr_t)smraw + 1023) & ~(uintptr_t)1023);
    const int tid = threadIdx.x, cta = blockIdx.x;
    const int wg = tid >> 7, wtid = tid & 127;
    const int wwid = wtid >> 5, lane = tid & 31;
    uint32_t smb = smem_u32_of(sm);
    uint32_t wgb = smb + (uint32_t)wg * WGSTRIDE;
    float* shz0 = (float*)(sm + ZOFF0);  // [32][36]
    float* shz1 = (float*)(sm + ZOFF1);  // [32][36]
    float* shzw = wg ? shz1 : shz0;
    float* shc = (float*)(sm + COFF);    // [2*32][9]
    float* shb = (float*)(sm + BIASOFF); // [2][32]

    for (int i = tid; i < 64; i += NTHR) {
        int l = i >> 5, m = i & 31;
        shb[i] = bias[l * G_ + (m >> 3) * 1024 + cta * 8 + (m & 7)];
    }
    for (int i = tid; i < 2 * 32 * 9; i += NTHR) shc[i] = 0.f;
    for (int i = cta * NTHR + tid; i < 32768; i += NCTA * NTHR)
        ((uint4*)g_Hb)[i] = make_uint4(0, 0, 0, 0);
    grid_sync();

    const int rowL = lane & 15, ksel = (lane >> 4) & 1;
    const int krL = lane & 15;
    const int eg = lane >> 2, etc = lane & 3;
    const int u = tid & 7, bq = tid >> 3;     // gate phase: one (b,u) per thread
    const int un = cta * 8 + u;

    for (int t = 0; t < T_; t++) {
        const int buf = t & 1, nbuf = buf ^ 1;
        for (int l = 0; l < 2; l++) {
            const unsigned char* img =
                (wg == 0) ? ((l == 0) ? (g_X + ((size_t)t << 17))
                                      : (g_Hb + ((size_t)nbuf << 17)))
                          : (g_Hb + ((size_t)(l * 2 + buf) << 17));

            float acc1[4][4], acc2[2][4];
            #pragma unroll
            for (int a = 0; a < 4; a++)
                #pragma unroll
                for (int k = 0; k < 4; k++) { acc1[a][k] = 0.f; if (a < 2) acc2[a][k] = 0.f; }

            auto issue = [&](int cc) {
                uint32_t stg = wgb + (uint32_t)(cc % 3) * STG_BYTES;
                size_t wbh = WB(l, wg, 0, cta, cc);
                size_t wbl = WB(l, wg, 1, cta, cc);
                #pragma unroll
                for (int j = 0; j < 16; j++) {
                    int gidx = wtid + j * 128;            // 0..2047
                    if (gidx < 512) {
                        uint32_t off = (uint32_t)gidx << 4;
                        cp16(stg + off, g_W + wbh + off);
                    } else if (gidx < 1024) {
                        uint32_t off = (uint32_t)(gidx - 512) << 4;
                        cp16(stg + 8192u + off, g_W + wbl + off);
                    } else {
                        int a = gidx - 1024;
                        int r = a >> 4, gi = a & 15;
                        cp16(stg + 16384u + (uint32_t)(r * 256 + gi * 16),
                             img + r * 2048 + cc * 256 + gi * 16);
                    }
                }
                CP_COMMIT();
            };

            issue(0); issue(1); issue(2);

            for (int c = 0; c < 8; c++) {
                if (c <= 5) { CP_WAIT2(); } else if (c == 6) { CP_WAIT1(); } else { CP_WAIT0(); }
                WG_BAR(wg + 1);
                uint32_t stg = wgb + (uint32_t)(c % 3) * STG_BYTES;
                uint32_t actb = stg + 16384u;
                #pragma unroll
                for (int kk = 0; kk < 128; kk += 16) {
                    uint32_t a[4][4], bh[2], bl[2];
                    int gA = (kk >> 3) + ksel;
                    #pragma unroll
                    for (int mt = 0; mt < 4; mt++) {
                        int row = mt * 16 + rowL;
                        uint32_t gp = (uint32_t)((gA & 8) | ((gA ^ (row & 7)) & 7));
                        LDSM4(a[mt], actb + (uint32_t)row * 256u + (gp << 4));
                    }
                    {
                        int kr = kk + krL;
                        uint32_t gp = (uint32_t)(wwid ^ ((kr >> 1) & 3));
                        uint32_t rb = stg + (uint32_t)kr * 64u + (gp << 4);
                        LDSM2T(bh, rb);
                        LDSM2T(bl, rb + 8192u);
                    }
                    #pragma unroll
                    for (int mt = 0; mt < 4; mt++)
                        MMA(acc1[mt], a[mt], bh[0], bh[1]);
                    #pragma unroll
                    for (int mt = 0; mt < 2; mt++)
                        MMA(acc2[mt], a[mt], bl[0], bl[1]);
                }
                WG_BAR(wg + 1);
                if (c < 5) issue(c + 3);
            }

            // epilogue: partial z = Whi*ahi + Whi*alo + Wlo*ahi into this wg's tile
            #pragma unroll
            for (int mt = 0; mt < 2; mt++)
                #pragma unroll
                for (int k = 0; k < 4; k++) {
                    float v = acc1[mt][k] + acc1[mt + 2][k] + acc2[mt][k];
                    int b = mt * 16 + eg + ((k >> 1) << 3);
                    int col = wwid * 8 + etc * 2 + (k & 1);
                    shzw[b * 36 + col] = v;
                }
            __syncthreads();

            // gate update + h publish: 256 threads, one (b,u) each
            {
                unsigned char* hdst = g_Hb + ((size_t)(l * 2 + nbuf) << 17);
                int b = bq;
                float zi = shz0[b * 36 + u]      + shz1[b * 36 + u]      + shb[l * 32 + u];
                float zf = shz0[b * 36 + 8 + u]  + shz1[b * 36 + 8 + u]  + shb[l * 32 + 8 + u];
                float zg = shz0[b * 36 + 16 + u] + shz1[b * 36 + 16 + u] + shb[l * 32 + 16 + u];
                float zo = shz0[b * 36 + 24 + u] + shz1[b * 36 + 24 + u] + shb[l * 32 + 24 + u];
                float* cp_ = &shc[(l * 32 + b) * 9 + u];
                float cold = *cp_;
                float ig = sigmoidf_(zi), fg = sigmoidf_(zf);
                float gg = tanhf(zg), og = sigmoidf_(zo);
                float cn = fg * cold + ig * gg;
                float hn = og * tanhf(cn);
                *cp_ = cn;
                __nv_bfloat16 hh = __float2bfloat16(hn);
                __nv_bfloat16 hl = __float2bfloat16(hn - __bfloat162float(hh));
                *(__nv_bfloat16*)(hdst + actoff(b, un)) = hh;
                *(__nv_bfloat16*)(hdst + actoff(b + 32, un)) = hl;
                if (l == 1) out[(size_t)b * T_ * H_ + (size_t)t * H_ + un] = hn;
                if (t == T_ - 1) {
                    out[OFFH + (size_t)(l * B_ + b) * H_ + un] = hn;
                    out[OFFC + (size_t)(l * B_ + b) * H_ + un] = cn;
                }
            }
            grid_sync();
        }
    }
}

extern "C" void kernel_launch(void* const* d_in, const int* in_sizes, int n_in,
                              void* d_out, int out_size) {
    const float* x = (const float*)d_in[0];
    const float* Wx = (const float*)d_in[1];
    const float* Wh = (const float*)d_in[2];
    const float* bias = (const float*)d_in[3];
    float* out = (float*)d_out;
    prep_w<<<dim3(16, 128, 4), 256>>>(Wx, Wh);
    prep_x<<<dim3(32, 512), 256>>>(x);
    cudaFuncSetAttribute(lstm_mma, cudaFuncAttributeMaxDynamicSharedMemorySize, DYNSM);
    lstm_mma<<<NCTA, NTHR, DYNSM>>>(bias, out);
}

// round 17
// speedup vs baseline: 9.6824x; 1.2476x over previous
#include <cuda_runtime.h>
#include <cuda_bf16.h>
#include <cstdint>

#define B_ 32
#define T_ 512
#define H_ 1024
#define G_ 4096
#define NCTA 128
#define NTHR 256
#define OFFH ((size_t)B_*T_*H_)
#define OFFC (OFFH + (size_t)2*B_*H_)
#define STG_BYTES 32768u
#define WGSTRIDE 98304u
#define ZA0 196608
#define ZA1 201216
#define ZB0 205824
#define ZB1 210432
#define COFF 215040
#define BIASOFF 217344
#define DYNSM 220160
#define DYNSM_PRE 230400

// W blocks: [l2][mat2][part2][cta128][chunk8] of 8KB = [k128][4 gran][16B] (gran = gate, XOR-swizzled)
#define WB(l,mat,part,cta,cc) ((size_t)(((((l)*2+(mat))*2+(part))*128 + (cta))*8 + (cc)) << 13)
__device__ __align__(1024) unsigned char g_W[67108864];
// x images per t: [64 rows (hi 0-31, lo 32-63)][2048 B], XOR-swizzled granules
__device__ __align__(1024) unsigned char g_X[67108864];
// h images: slots 0,1 = h0 (by parity), 2,3 = h1
__device__ __align__(1024) unsigned char g_Hb[524288];
// precomputed x@Wx0: [t][cta][b][32 cols] f32
__device__ float g_ZX[(size_t)67108864];
__device__ unsigned g_bar_count = 0;
__device__ unsigned g_bar_gen = 0;

__device__ __forceinline__ uint32_t smem_u32_of(const void* p) {
    uint32_t a;
    asm("{ .reg .u64 t; cvta.to.shared.u64 t, %1; cvt.u32.u64 %0, t; }" : "=r"(a) : "l"(p));
    return a;
}
__device__ __forceinline__ void cp16(uint32_t d, const void* s) {
    asm volatile("cp.async.cg.shared.global [%0], [%1], 16;" :: "r"(d), "l"(s));
}
#define CP_COMMIT() asm volatile("cp.async.commit_group;" ::: "memory")
#define CP_WAIT2() asm volatile("cp.async.wait_group 2;" ::: "memory")
#define CP_WAIT1() asm volatile("cp.async.wait_group 1;" ::: "memory")
#define CP_WAIT0() asm volatile("cp.async.wait_group 0;" ::: "memory")
#define WG_BAR(id) asm volatile("bar.sync %0, 128;" :: "r"(id) : "memory")
#define LDSM4(r, a) asm volatile("ldmatrix.sync.aligned.m8n8.x4.shared.b16 {%0,%1,%2,%3}, [%4];" \
    : "=r"((r)[0]),"=r"((r)[1]),"=r"((r)[2]),"=r"((r)[3]) : "r"(a))
#define LDSM2T(r, a) asm volatile("ldmatrix.sync.aligned.m8n8.x2.trans.shared.b16 {%0,%1}, [%2];" \
    : "=r"((r)[0]),"=r"((r)[1]) : "r"(a))
#define MMA(d, a, b0, b1) asm volatile( \
    "mma.sync.aligned.m16n8k16.row.col.f32.bf16.bf16.f32 {%0,%1,%2,%3},{%4,%5,%6,%7},{%8,%9},{%0,%1,%2,%3};" \
    : "+f"((d)[0]),"+f"((d)[1]),"+f"((d)[2]),"+f"((d)[3]) \
    : "r"((a)[0]),"r"((a)[1]),"r"((a)[2]),"r"((a)[3]), "r"(b0),"r"(b1))

__device__ __forceinline__ float sigmoidf_(float v) { return 1.0f / (1.0f + __expf(-v)); }

__device__ __forceinline__ void grid_sync() {
    __threadfence();
    __syncthreads();
    if (threadIdx.x == 0) {
        unsigned gen;
        asm volatile("ld.acquire.gpu.global.b32 %0, [%1];" : "=r"(gen) : "l"(&g_bar_gen));
        unsigned arrived = atomicAdd(&g_bar_count, 1u);
        if (arrived == NCTA - 1) {
            atomicExch(&g_bar_count, 0u);
            __threadfence();
            asm volatile("red.release.gpu.global.add.u32 [%0], 1;" :: "l"(&g_bar_gen) : "memory");
        } else {
            unsigned cur;
            do {
                __nanosleep(20);
                asm volatile("ld.acquire.gpu.global.b32 %0, [%1];" : "=r"(cur) : "l"(&g_bar_gen));
            } while (cur == gen);
        }
    }
    __syncthreads();
}

// act image byte offset (pitch 2048 B, k in bf16 units), XOR-low3 granule swizzle
__device__ __forceinline__ uint32_t actoff(int r, int k) {
    int g = k >> 3;
    int gp = (g & ~7) | ((g ^ (r & 7)) & 7);
    return (uint32_t)(r * 2048 + gp * 16 + (k & 7) * 2);
}

__global__ void prep_w(const float* __restrict__ Wx, const float* __restrict__ Wh) {
    int lm = blockIdx.z, l = lm >> 1, mat = lm & 1;
    const float* W = (mat ? Wh : Wx) + (size_t)l * H_ * G_;
    int col = blockIdx.x * 256 + threadIdx.x;
    int cta = (col & 1023) >> 3, uu = col & 7, gate = col >> 10;
    size_t bhi = WB(l, mat, 0, cta, 0);
    size_t blo = WB(l, mat, 1, cta, 0);
    #pragma unroll
    for (int i = 0; i < 8; i++) {
        int k = blockIdx.y * 8 + i;
        float f = W[(size_t)k * G_ + col];
        __nv_bfloat16 hi = __float2bfloat16(f);
        __nv_bfloat16 lo = __float2bfloat16(f - __bfloat162float(hi));
        int cc = k >> 7, krow = k & 127;
        int gp = gate ^ ((krow >> 1) & 3);
        size_t off = ((size_t)cc << 13) + krow * 64 + gp * 16 + uu * 2;
        *(__nv_bfloat16*)(g_W + bhi + off) = hi;
        *(__nv_bfloat16*)(g_W + blo + off) = lo;
    }
}

__global__ void prep_x(const float* __restrict__ x) {
    int t = blockIdx.y;
    int g = blockIdx.x * 256 + threadIdx.x;
    int b = g >> 8, kq = (g & 255) * 4;
    float4 v = *(const float4*)(x + ((size_t)b * T_ + t) * H_ + kq);
    float f[4] = {v.x, v.y, v.z, v.w};
    __align__(8) __nv_bfloat16 hv[4], lv[4];
    #pragma unroll
    for (int r = 0; r < 4; r++) {
        hv[r] = __float2bfloat16(f[r]);
        lv[r] = __float2bfloat16(f[r] - __bfloat162float(hv[r]));
    }
    unsigned char* img = g_X + ((size_t)t << 17);
    *(uint2*)(img + actoff(b, kq)) = *(uint2*)hv;
    *(uint2*)(img + actoff(b + 32, kq)) = *(uint2*)lv;
}

// ---- precompute zx = x @ Wx[0] for all t (weights SMEM-resident) ----
extern "C" __global__ void __launch_bounds__(NTHR, 1) pre_zx() {
    extern __shared__ unsigned char smraw[];
    unsigned char* sm = (unsigned char*)(((uintptr_t)smraw + 1023) & ~(uintptr_t)1023);
    uint32_t smb = smem_u32_of(sm);
    const int tid = threadIdx.x, cta = blockIdx.x;
    const int wg = tid >> 7, wtid = tid & 127;
    const int wwid = wtid >> 5, lane = tid & 31;

    // load Wx0 hi/lo for this CTA's 32 cols: 8 chunks x 16KB resident
    #pragma unroll
    for (int j = 0; j < 32; j++) {
        int gidx = tid + j * 256;
        int c = gidx >> 10, within = gidx & 1023, part = within >> 9;
        uint32_t off = (uint32_t)(within & 511) << 4;
        cp16(smb + (uint32_t)c * 16384u + (uint32_t)part * 8192u + off,
             g_W + WB(0, 0, part, cta, c) + off);
    }
    CP_COMMIT(); CP_WAIT0();
    __syncthreads();

    uint32_t stb = smb + 131072u + (uint32_t)wg * 49152u;
    auto issueA = [&](int i) {
        int c = i & 7, t = (i >> 3) * 2 + wg;
        const unsigned char* img = g_X + ((size_t)t << 17);
        uint32_t stg = stb + (uint32_t)(i % 3) * 16384u;
        #pragma unroll
        for (int j = 0; j < 8; j++) {
            int gidx = wtid + j * 128;
            int r = gidx >> 4, gi = gidx & 15;
            cp16(stg + (uint32_t)(r * 256 + gi * 16), img + r * 2048 + c * 256 + gi * 16);
        }
        CP_COMMIT();
    };
    const int rowL = lane & 15, ksel = (lane >> 4) & 1, krL = lane & 15;
    const int eg = lane >> 2, etc = lane & 3;

    issueA(0); issueA(1); issueA(2);
    float acc1[4][4], acc2[2][4];
    #pragma unroll 1
    for (int i = 0; i < 2048; i++) {
        int c = i & 7, t = (i >> 3) * 2 + wg;
        if (c == 0) {
            #pragma unroll
            for (int a = 0; a < 4; a++)
                #pragma unroll
                for (int k = 0; k < 4; k++) { acc1[a][k] = 0.f; if (a < 2) acc2[a][k] = 0.f; }
        }
        int pend = ((3 + i) < 2048 ? (3 + i) : 2048) - i - 1;
        if (pend >= 2) { CP_WAIT2(); } else if (pend == 1) { CP_WAIT1(); } else { CP_WAIT0(); }
        WG_BAR(wg + 1);
        uint32_t actb = stb + (uint32_t)(i % 3) * 16384u;
        uint32_t wres = smb + (uint32_t)c * 16384u;
        #pragma unroll
        for (int kk = 0; kk < 128; kk += 16) {
            uint32_t a[4][4], bh[2], bl[2];
            int gA = (kk >> 3) + ksel;
            #pragma unroll
            for (int mt = 0; mt < 4; mt++) {
                int row = mt * 16 + rowL;
                uint32_t gp = (uint32_t)((gA & 8) | ((gA ^ (row & 7)) & 7));
                LDSM4(a[mt], actb + (uint32_t)row * 256u + (gp << 4));
            }
            {
                int kr = kk + krL;
                uint32_t gp = (uint32_t)(wwid ^ ((kr >> 1) & 3));
                uint32_t rb = wres + (uint32_t)kr * 64u + (gp << 4);
                LDSM2T(bh, rb);
                LDSM2T(bl, rb + 8192u);
            }
            #pragma unroll
            for (int mt = 0; mt < 4; mt++) MMA(acc1[mt], a[mt], bh[0], bh[1]);
            #pragma unroll
            for (int mt = 0; mt < 2; mt++) MMA(acc2[mt], a[mt], bl[0], bl[1]);
        }
        WG_BAR(wg + 1);
        if (i + 3 < 2048) issueA(i + 3);
        if (c == 7) {
            float* zdst = g_ZX + ((size_t)t * 128 + cta) * 1024;
            #pragma unroll
            for (int mt = 0; mt < 2; mt++)
                #pragma unroll
                for (int k = 0; k < 4; k++) {
                    float v = acc1[mt][k] + acc1[mt + 2][k] + acc2[mt][k];
                    int b = mt * 16 + eg + ((k >> 1) << 3);
                    int col = wwid * 8 + etc * 2 + (k & 1);
                    zdst[b * 32 + col] = v;
                }
        }
    }
}

// ---- main persistent kernel: 1 barrier per timestep, fused l1@p + l0@p+1 ----
extern "C" __global__ void __launch_bounds__(NTHR, 1)
lstm_mma(const float* __restrict__ bias, float* __restrict__ out) {
    extern __shared__ unsigned char smraw[];
    unsigned char* sm = (unsigned char*)(((uintptr_t)smraw + 1023) & ~(uintptr_t)1023);
    const int tid = threadIdx.x, cta = blockIdx.x;
    const int wg = tid >> 7, wtid = tid & 127;
    const int wwid = wtid >> 5, lane = tid & 31;
    uint32_t smb = smem_u32_of(sm);
    uint32_t wgb = smb + (uint32_t)wg * WGSTRIDE;
    float* shzA0 = (float*)(sm + ZA0);
    float* shzA1 = (float*)(sm + ZA1);
    float* shzB0 = (float*)(sm + ZB0);
    float* shzB1 = (float*)(sm + ZB1);
    float* shzA = wg ? shzA1 : shzA0;
    float* shzB = wg ? shzB1 : shzB0;
    float* shc = (float*)(sm + COFF);    // [2*32][9]
    float* shb = (float*)(sm + BIASOFF); // [2][32]

    for (int i = tid; i < 64; i += NTHR) {
        int l = i >> 5, m = i & 31;
        shb[i] = bias[l * G_ + (m >> 3) * 1024 + cta * 8 + (m & 7)];
    }
    for (int i = tid; i < 2 * 32 * 9; i += NTHR) shc[i] = 0.f;
    for (int i = cta * NTHR + tid; i < 32768; i += NCTA * NTHR)
        ((uint4*)g_Hb)[i] = make_uint4(0, 0, 0, 0);
    grid_sync();

    const int rowL = lane & 15, ksel = (lane >> 4) & 1, krL = lane & 15;
    const int eg = lane >> 2, etc = lane & 3;
    const int u = tid & 7, bq = tid >> 3;
    const int un = cta * 8 + u;

    // ---- prologue: l0 @ t=0 (h_prev = 0 -> z = zx[0] + bias) ----
    {
        const float* zp = g_ZX + ((size_t)cta) * 1024 + bq * 32;
        float zi = __ldg(zp + u)      + shb[u];
        float zf = __ldg(zp + 8 + u)  + shb[8 + u];
        float zg = __ldg(zp + 16 + u) + shb[16 + u];
        float zo = __ldg(zp + 24 + u) + shb[24 + u];
        float ig = sigmoidf_(zi), gg = tanhf(zg), og = sigmoidf_(zo);
        (void)zf;
        float cn = ig * gg;
        float hn = og * tanhf(cn);
        shc[(0 * 32 + bq) * 9 + u] = cn;
        unsigned char* hdst = g_Hb;  // h0 slot 0
        __nv_bfloat16 hh = __float2bfloat16(hn);
        __nv_bfloat16 hl = __float2bfloat16(hn - __bfloat162float(hh));
        *(__nv_bfloat16*)(hdst + actoff(bq, un)) = hh;
        *(__nv_bfloat16*)(hdst + actoff(bq + 32, un)) = hl;
    }
    grid_sync();

    #pragma unroll 1
    for (int p = 0; p < T_; p++) {
        const unsigned char* img_h0p = g_Hb + ((size_t)(p & 1) << 17);
        const unsigned char* img_h1  = g_Hb + ((size_t)(2 + ((p + 1) & 1)) << 17);
        const int nc = (p < T_ - 1) ? 12 : 8;

        // prefetch zx[p+1] into regs (hidden behind GEMMs)
        float zxr[4] = {0.f, 0.f, 0.f, 0.f};
        if (p < T_ - 1) {
            const float* zp = g_ZX + ((size_t)(p + 1) * 128 + cta) * 1024 + bq * 32;
            zxr[0] = __ldg(zp + u);      zxr[1] = __ldg(zp + 8 + u);
            zxr[2] = __ldg(zp + 16 + u); zxr[3] = __ldg(zp + 24 + u);
        }

        auto issue = [&](int i) {
            int l, mat, cc; const unsigned char* img;
            if (i < 8) { l = 1; mat = wg; cc = i; img = (wg == 0) ? img_h0p : img_h1; }
            else       { l = 0; mat = 1; cc = (wg == 0) ? (i - 8) : (i - 4); img = img_h0p; }
            uint32_t stg = wgb + (uint32_t)(i % 3) * STG_BYTES;
            size_t wbh = WB(l, mat, 0, cta, cc);
            size_t wbl = WB(l, mat, 1, cta, cc);
            #pragma unroll
            for (int j = 0; j < 16; j++) {
                int gidx = wtid + j * 128;
                if (gidx < 512) {
                    uint32_t off = (uint32_t)gidx << 4;
                    cp16(stg + off, g_W + wbh + off);
                } else if (gidx < 1024) {
                    uint32_t off = (uint32_t)(gidx - 512) << 4;
                    cp16(stg + 8192u + off, g_W + wbl + off);
                } else {
                    int a = gidx - 1024;
                    int r = a >> 4, gi = a & 15;
                    cp16(stg + 16384u + (uint32_t)(r * 256 + gi * 16),
                         img + r * 2048 + cc * 256 + gi * 16);
                }
            }
            CP_COMMIT();
        };

        issue(0); issue(1); issue(2);
        float acc1[4][4], acc2[2][4];
        #pragma unroll
        for (int a = 0; a < 4; a++)
            #pragma unroll
            for (int k = 0; k < 4; k++) { acc1[a][k] = 0.f; if (a < 2) acc2[a][k] = 0.f; }

        #pragma unroll 1
        for (int i = 0; i < nc; i++) {
            int pend = ((3 + i) < nc ? (3 + i) : nc) - i - 1;
            if (pend >= 2) { CP_WAIT2(); } else if (pend == 1) { CP_WAIT1(); } else { CP_WAIT0(); }
            WG_BAR(wg + 1);
            uint32_t stg = wgb + (uint32_t)(i % 3) * STG_BYTES;
            uint32_t actb = stg + 16384u;
            #pragma unroll
            for (int kk = 0; kk < 128; kk += 16) {
                uint32_t a[4][4], bh[2], bl[2];
                int gA = (kk >> 3) + ksel;
                #pragma unroll
                for (int mt = 0; mt < 4; mt++) {
                    int row = mt * 16 + rowL;
                    uint32_t gp = (uint32_t)((gA & 8) | ((gA ^ (row & 7)) & 7));
                    LDSM4(a[mt], actb + (uint32_t)row * 256u + (gp << 4));
                }
                {
                    int kr = kk + krL;
                    uint32_t gp = (uint32_t)(wwid ^ ((kr >> 1) & 3));
                    uint32_t rb = stg + (uint32_t)kr * 64u + (gp << 4);
                    LDSM2T(bh, rb);
                    LDSM2T(bl, rb + 8192u);
                }
                #pragma unroll
                for (int mt = 0; mt < 4; mt++) MMA(acc1[mt], a[mt], bh[0], bh[1]);
                #pragma unroll
                for (int mt = 0; mt < 2; mt++) MMA(acc2[mt], a[mt], bl[0], bl[1]);
            }
            WG_BAR(wg + 1);
            if (i + 3 < nc) issue(i + 3);
            if (i == 7 || i == nc - 1) {
                float* zt = (i == 7) ? shzA : shzB;
                #pragma unroll
                for (int mt = 0; mt < 2; mt++)
                    #pragma unroll
                    for (int k = 0; k < 4; k++) {
                        float v = acc1[mt][k] + acc1[mt + 2][k] + acc2[mt][k];
                        int b = mt * 16 + eg + ((k >> 1) << 3);
                        int col = wwid * 8 + etc * 2 + (k & 1);
                        zt[b * 36 + col] = v;
                    }
                #pragma unroll
                for (int a = 0; a < 4; a++)
                    #pragma unroll
                    for (int k = 0; k < 4; k++) { acc1[a][k] = 0.f; if (a < 2) acc2[a][k] = 0.f; }
            }
        }
        __syncthreads();

        // ---- gate l1 @ t=p ----
        {
            int b = bq;
            float zi = shzA0[b * 36 + u]      + shzA1[b * 36 + u]      + shb[32 + u];
            float zf = shzA0[b * 36 + 8 + u]  + shzA1[b * 36 + 8 + u]  + shb[40 + u];
            float zg = shzA0[b * 36 + 16 + u] + shzA1[b * 36 + 16 + u] + shb[48 + u];
            float zo = shzA0[b * 36 + 24 + u] + shzA1[b * 36 + 24 + u] + shb[56 + u];
            float* cp_ = &shc[(32 + b) * 9 + u];
            float cold = *cp_;
            float ig = sigmoidf_(zi), fg = sigmoidf_(zf);
            float gg = tanhf(zg), og = sigmoidf_(zo);
            float cn = fg * cold + ig * gg;
            float hn = og * tanhf(cn);
            *cp_ = cn;
            unsigned char* hdst = g_Hb + ((size_t)(2 + (p & 1)) << 17);
            __nv_bfloat16 hh = __float2bfloat16(hn);
            __nv_bfloat16 hl = __float2bfloat16(hn - __bfloat162float(hh));
            *(__nv_bfloat16*)(hdst + actoff(b, un)) = hh;
            *(__nv_bfloat16*)(hdst + actoff(b + 32, un)) = hl;
            out[(size_t)b * T_ * H_ + (size_t)p * H_ + un] = hn;
            if (p == T_ - 1) {
                out[OFFH + (size_t)(B_ + b) * H_ + un] = hn;
                out[OFFC + (size_t)(B_ + b) * H_ + un] = cn;
            }
        }
        // ---- gate l0 @ t=p+1 ----
        if (p < T_ - 1) {
            int b = bq;
            float zi = shzB0[b * 36 + u]      + shzB1[b * 36 + u]      + zxr[0] + shb[u];
            float zf = shzB0[b * 36 + 8 + u]  + shzB1[b * 36 + 8 + u]  + zxr[1] + shb[8 + u];
            float zg = shzB0[b * 36 + 16 + u] + shzB1[b * 36 + 16 + u] + zxr[2] + shb[16 + u];
            float zo = shzB0[b * 36 + 24 + u] + shzB1[b * 36 + 24 + u] + zxr[3] + shb[24 + u];
            float* cp_ = &shc[(0 + b) * 9 + u];
            float cold = *cp_;
            float ig = sigmoidf_(zi), fg = sigmoidf_(zf);
            float gg = tanhf(zg), og = sigmoidf_(zo);
            float cn = fg * cold + ig * gg;
            float hn = og * tanhf(cn);
            *cp_ = cn;
            unsigned char* hdst = g_Hb + ((size_t)((p + 1) & 1) << 17);
            __nv_bfloat16 hh = __float2bfloat16(hn);
            __nv_bfloat16 hl = __float2bfloat16(hn - __bfloat162float(hh));
            *(__nv_bfloat16*)(hdst + actoff(b, un)) = hh;
            *(__nv_bfloat16*)(hdst + actoff(b + 32, un)) = hl;
            if (p == T_ - 2) {
                out[OFFH + (size_t)b * H_ + un] = hn;
                out[OFFC + (size_t)b * H_ + un] = cn;
            }
        }
        grid_sync();
    }
}

extern "C" void kernel_launch(void* const* d_in, const int* in_sizes, int n_in,
                              void* d_out, int out_size) {
    const float* x = (const float*)d_in[0];
    const float* Wx = (const float*)d_in[1];
    const float* Wh = (const float*)d_in[2];
    const float* bias = (const float*)d_in[3];
    float* out = (float*)d_out;
    prep_w<<<dim3(16, 128, 4), 256>>>(Wx, Wh);
    prep_x<<<dim3(32, 512), 256>>>(x);
    cudaFuncSetAttribute(pre_zx, cudaFuncAttributeMaxDynamicSharedMemorySize, DYNSM_PRE);
    pre_zx<<<NCTA, NTHR, DYNSM_PRE>>>();
    cudaFuncSetAttribute(lstm_mma, cudaFuncAttributeMaxDynamicSharedMemorySize, DYNSM);
    lstm_mma<<<NCTA, NTHR, DYNSM>>>(bias, out);
}